// round 9
// baseline (speedup 1.0000x reference)
#include <cuda_runtime.h>
#include <cuda_fp16.h>
#include <cuda_fp8.h>
#include <cstdint>

#define KDIM 4096
#define MDIM 8192
#define NDIM 4096
#define NGRP 128              // K / 32 groups per row

#define BM 128
#define BN 128
#define BK 64                 // 2 groups per mainloop iter
#define STAGES 6
#define KSTEPS (KDIM / BK)    // 64
#define B_OFF 8192
#define SA_OFF 16384
#define SB_OFF 17408
#define STAGE_BYTES 18432
#define SMEM_TOTAL (STAGES * STAGE_BYTES)   // 110592 B

// Quantized operands (raw e4m3 bytes) + per-group fp32 scales
__device__ __align__(1024) uint8_t g_qA[(size_t)MDIM * KDIM];  // 32 MB
__device__ __align__(1024) uint8_t g_qB[(size_t)NDIM * KDIM];  // 16 MB
__device__ __align__(1024) float   g_sA[(size_t)MDIM * NGRP];  //  4 MB
__device__ __align__(1024) float   g_sB[(size_t)NDIM * NGRP];  //  2 MB

// ---------------------------------------------------------------------------
// PTX helpers
// ---------------------------------------------------------------------------
__device__ __forceinline__ uint32_t s2u(const void* p) {
    return (uint32_t)__cvta_generic_to_shared(p);
}
__device__ __forceinline__ void cp16(uint32_t s, const void* g) {
    asm volatile("cp.async.cg.shared.global [%0], [%1], 16;" :: "r"(s), "l"(g) : "memory");
}
__device__ __forceinline__ void cp8(uint32_t s, const void* g) {
    asm volatile("cp.async.ca.shared.global [%0], [%1], 8;" :: "r"(s), "l"(g) : "memory");
}
__device__ __forceinline__ void cp_commit() {
    asm volatile("cp.async.commit_group;" ::: "memory");
}
__device__ __forceinline__ void cp_wait4() {
    asm volatile("cp.async.wait_group 4;" ::: "memory");
}
__device__ __forceinline__ void ldsm4(uint32_t* r, uint32_t addr) {
    asm volatile("ldmatrix.sync.aligned.m8n8.x4.shared.b16 {%0,%1,%2,%3}, [%4];"
                 : "=r"(r[0]), "=r"(r[1]), "=r"(r[2]), "=r"(r[3]) : "r"(addr));
}
// fp8 e4m3 MMA: one instruction = one full 32-wide quant group
__device__ __forceinline__ void mma16832(float* d, const uint32_t* a,
                                         const uint32_t* b, const float* c) {
    asm volatile(
        "mma.sync.aligned.m16n8k32.row.col.f32.e4m3.e4m3.f32 "
        "{%0,%1,%2,%3}, {%4,%5,%6,%7}, {%8,%9}, {%10,%11,%12,%13};"
        : "=f"(d[0]), "=f"(d[1]), "=f"(d[2]), "=f"(d[3])
        : "r"(a[0]), "r"(a[1]), "r"(a[2]), "r"(a[3]), "r"(b[0]), "r"(b[1]),
          "f"(c[0]), "f"(c[1]), "f"(c[2]), "f"(c[3]));
}

// ---------------------------------------------------------------------------
// Quantize: q = fp8_e4m3(v / scale) stored as raw e4m3 byte; scale fp32.
// dest flag selects device-global buffers IN DEVICE CODE.
// One thread = 4 consecutive K (float4); 8-lane shuffle amax per 32-group.
// ---------------------------------------------------------------------------
__global__ void quant_kernel(const float* __restrict__ src, int dest) {
    uint8_t* __restrict__ qdst = dest ? g_qB : g_qA;
    float*   __restrict__ sdst = dest ? g_sB : g_sA;

    long long t = (long long)blockIdx.x * blockDim.x + threadIdx.x;
    long long row = t >> 10;            // 1024 float4 per row
    int f4 = (int)(t & 1023);

    const float4 v4 = reinterpret_cast<const float4*>(src)[t];
    float a = fmaxf(fmaxf(fabsf(v4.x), fabsf(v4.y)),
                    fmaxf(fabsf(v4.z), fabsf(v4.w)));
    a = fmaxf(a, __shfl_xor_sync(0xffffffffu, a, 1));
    a = fmaxf(a, __shfl_xor_sync(0xffffffffu, a, 2));
    a = fmaxf(a, __shfl_xor_sync(0xffffffffu, a, 4));
    float scale = __fdiv_rn(fmaxf(a, 1e-8f), 448.0f);

    float vv[4] = {v4.x, v4.y, v4.z, v4.w};
    uint32_t bytes = 0;
#pragma unroll
    for (int i = 0; i < 4; i++) {
        float q = __fdiv_rn(vv[i], scale);
        __nv_fp8_storage_t s8 =
            __nv_cvt_float_to_fp8(q, __NV_SATFINITE, __NV_E4M3);  // RNE, satfinite
        bytes |= (uint32_t)s8 << (8 * i);
    }
    *reinterpret_cast<uint32_t*>(qdst + ((size_t)row << 12) + f4 * 4) = bytes;

    if ((f4 & 7) == 0)
        sdst[(size_t)row * NGRP + (f4 >> 3)] = scale;
}

// ---------------------------------------------------------------------------
// GEMM: out[M,N] = sum_g (qA_g . qB_g)_fp8mma * sA[m,g] * sB[n,g] + bias[n]
// 128x128 CTA tile, BK=64 (2 groups), 6-stage cp.async, 8 warps (2M x 4N).
// Smem rows are 64 B; 16B-chunk swizzle: c ^= (row>>1)&3 (ldmatrix conflict-free).
// ---------------------------------------------------------------------------
__global__ void __launch_bounds__(256, 1)
gemm_kernel(const float* __restrict__ bias, float* __restrict__ out) {
    extern __shared__ __align__(1024) char smem_raw[];
    const uint32_t sbase = s2u(smem_raw);
    const int tid  = threadIdx.x;
    const int lane = tid & 31;
    const int warp = tid >> 5;
    const int warpM = warp & 1;          // 2 x 64 rows
    const int warpN = warp >> 1;         // 4 x 32 cols

    // Grid swizzle: 16-wide N super-columns
    const int gid = blockIdx.x;
    const int sc  = gid >> 10;
    const int rem = gid & 1023;
    const int blockN = ((sc << 4) | (rem & 15)) * BN;
    const int blockM = (rem >> 4) * BM;

    // ldmatrix lane addressing (fp8-k32 via b16 x4 quadrant trick)
    const int aRow = warpM * 64 + (lane & 15);
    const int aC   = lane >> 4;                       // k-half select
    const int aSw  = (aRow >> 1) & 3;
    const int bN   = warpN * 32 + (lane & 7) + ((lane >> 4) << 3);
    const int bC   = (lane >> 3) & 1;                 // k-half select
    const int bSw  = (bN >> 1) & 3;
    const int rsIdx = warpM * 64 + (lane >> 2);
    const int csIdx = warpN * 32 + ((lane & 3) << 1);

    const uint8_t* gA  = g_qA + (size_t)blockM * KDIM;
    const uint8_t* gB  = g_qB + (size_t)blockN * KDIM;
    const float*   gsA = g_sA + (size_t)blockM * NGRP;
    const float*   gsB = g_sB + (size_t)blockN * NGRP;

    float acc[64];
#pragma unroll
    for (int i = 0; i < 64; i++) acc[i] = 0.0f;
    const float zf[4] = {0.f, 0.f, 0.f, 0.f};

    auto load_stage = [&](int stage, int kb) {
        uint32_t st = sbase + stage * STAGE_BYTES;
#pragma unroll
        for (int u = 0; u < 2; u++) {            // A: 512 x 16B chunks
            int idx = tid + u * 256;
            int row = idx >> 2, c = idx & 3;
            cp16(st + row * 64 + ((c ^ ((row >> 1) & 3)) << 4),
                 gA + (size_t)row * KDIM + kb * 64 + c * 16);
        }
#pragma unroll
        for (int u = 0; u < 2; u++) {            // B: 512 x 16B chunks
            int idx = tid + u * 256;
            int row = idx >> 2, c = idx & 3;
            cp16(st + B_OFF + row * 64 + ((c ^ ((row >> 1) & 3)) << 4),
                 gB + (size_t)row * KDIM + kb * 64 + c * 16);
        }
        if (tid < 128)
            cp8(st + SA_OFF + tid * 8, gsA + (size_t)tid * NGRP + kb * 2);
        else
            cp8(st + SB_OFF + (tid - 128) * 8,
                gsB + (size_t)(tid - 128) * NGRP + kb * 2);
    };

#pragma unroll
    for (int s = 0; s < 5; s++) { load_stage(s, s); cp_commit(); }

    for (int kb = 0; kb < KSTEPS; kb++) {
        cp_wait4();
        __syncthreads();
        const int stage = kb % STAGES;
        const uint32_t st = sbase + stage * STAGE_BYTES;
        const float2* sAf2 = reinterpret_cast<const float2*>(
            smem_raw + stage * STAGE_BYTES + SA_OFF);
        const float2* sBf2 = reinterpret_cast<const float2*>(
            smem_raw + stage * STAGE_BYTES + SB_OFF);

        float2 sLo[4], sHi[4], sC0[4], sC1[4];
#pragma unroll
        for (int i = 0; i < 4; i++) {
            sLo[i] = sAf2[rsIdx + i * 16];
            sHi[i] = sAf2[rsIdx + i * 16 + 8];
        }
#pragma unroll
        for (int j = 0; j < 4; j++) {
            sC0[j] = sBf2[csIdx + j * 8];
            sC1[j] = sBf2[csIdx + j * 8 + 1];
        }

#pragma unroll
        for (int g = 0; g < 2; g++) {
            uint32_t afr[4][4], bfr[2][4];
#pragma unroll
            for (int i = 0; i < 4; i++)
                ldsm4(afr[i], st + (aRow + i * 16) * 64 +
                              (((g * 2 + aC) ^ aSw) << 4));
#pragma unroll
            for (int jp = 0; jp < 2; jp++)
                ldsm4(bfr[jp], st + B_OFF + (bN + jp * 16) * 64 +
                               (((g * 2 + bC) ^ bSw) << 4));
#pragma unroll
            for (int i = 0; i < 4; i++) {
                const float rlo = g ? sLo[i].y : sLo[i].x;
                const float rhi = g ? sHi[i].y : sHi[i].x;
#pragma unroll
                for (int j = 0; j < 4; j++) {
                    const float c0 = g ? sC0[j].y : sC0[j].x;
                    const float c1 = g ? sC1[j].y : sC1[j].x;
                    float t[4];
                    mma16832(t, afr[i], &bfr[j >> 1][(j & 1) * 2], zf);
                    float* A_ = &acc[((i << 2) + j) << 2];
                    A_[0] = fmaf(t[0], rlo * c0, A_[0]);
                    A_[1] = fmaf(t[1], rlo * c1, A_[1]);
                    A_[2] = fmaf(t[2], rhi * c0, A_[2]);
                    A_[3] = fmaf(t[3], rhi * c1, A_[3]);
                }
            }
        }
        if (kb + 5 < KSTEPS) load_stage((kb + 5) % STAGES, kb + 5);
        cp_commit();   // uniform group count per iteration
    }

    // Epilogue: bias add + fp32 store
#pragma unroll
    for (int i = 0; i < 4; i++) {
        const int r0 = blockM + warpM * 64 + i * 16 + (lane >> 2);
#pragma unroll
        for (int j = 0; j < 4; j++) {
            const int c = blockN + warpN * 32 + j * 8 + ((lane & 3) << 1);
            const float2 bb = __ldg(reinterpret_cast<const float2*>(bias + c));
            const float* A_ = &acc[((i << 2) + j) << 2];
            float2 v0 = {A_[0] + bb.x, A_[1] + bb.y};
            float2 v1 = {A_[2] + bb.x, A_[3] + bb.y};
            *reinterpret_cast<float2*>(out + (size_t)r0 * NDIM + c) = v0;
            *reinterpret_cast<float2*>(out + (size_t)(r0 + 8) * NDIM + c) = v1;
        }
    }
}

// ---------------------------------------------------------------------------
extern "C" void kernel_launch(void* const* d_in, const int* in_sizes, int n_in,
                              void* d_out, int out_size) {
    const float* x    = (const float*)d_in[0];   // [4,2048,4096] fp32
    const float* W    = (const float*)d_in[1];   // [4096,4096]   fp32
    const float* bias = (const float*)d_in[2];   // [4096]        fp32
    float* out = (float*)d_out;                  // [8192,4096]   fp32

    cudaFuncSetAttribute(gemm_kernel,
                         cudaFuncAttributeMaxDynamicSharedMemorySize, SMEM_TOTAL);

    quant_kernel<<<(MDIM * 1024) / 256, 256>>>(x, 0);   // -> g_qA, g_sA
    quant_kernel<<<(NDIM * 1024) / 256, 256>>>(W, 1);   // -> g_qB, g_sB
    gemm_kernel<<<(MDIM / BM) * (NDIM / BN), 256, SMEM_TOTAL>>>(bias, out);
}